// round 17
// baseline (speedup 1.0000x reference)
#include <cuda_runtime.h>
#include <math.h>

#define NSTEPS 130
#define NLUT   27
#define ROWS   32
#define UROWS  132          // 130 data rows + 2 padding rows for tail prefetch

// srcA[l] / srcB[l]: flat-state index feeding mux selects A / B of LUT-lane l.
// Lanes 27..31 are constant-carrier lanes (self-wired).
__device__ __constant__ int c_srcA[32] = {
    1, 3, 3,   7, 0, 0,   4, 6, 6,   19, 12, 12,  16, 9, 9,
    13, 15, 15, 10, 18, 18, 22, 6, 6, 25, 15, 15,
    27, 28, 29, 30, 31};
__device__ __constant__ int c_srcB[32] = {
    17, 17, 1,  5, 5, 7,   11, 11, 4, 8, 8, 19,   28, 28, 16,
    2, 2, 13,   27, 27, 10, 23, 23, 22, 26, 26, 25,
    27, 28, 29, 30, 31};

#define BAR_ARRIVE(b) asm volatile("bar.arrive %0, 64;" :: "r"(b) : "memory")
#define BAR_WAIT(b)   asm volatile("bar.sync %0, 64;"   :: "r"(b) : "memory")

// Compile-time producer batch: CNT<=16 rows starting at S0. Front-batched
// LDGs (constant indices -> full MLP), then coefficient math + STS.
template <int S0, int CNT>
__device__ __forceinline__ void produce(const float4* __restrict__ noise4,
                                        float4* __restrict__ s_uvrs,
                                        int nl, bool act, float4 wb,
                                        float c0, float c1, float c2, float c3,
                                        float xv, int lane) {
    float4 nb[CNT];
#pragma unroll
    for (int i = 0; i < CNT; ++i)
        nb[i] = noise4[(S0 + i) * NLUT + nl];
#pragma unroll
    for (int i = 0; i < CNT; ++i) {
        const float4 n = nb[i];
        const float w0 = fmaf(c0, n.x, wb.x);
        const float w1 = fmaf(c1, n.y, wb.y);
        const float w2 = fmaf(c2, n.z, wb.z);
        const float w3 = fmaf(c3, n.w, wb.w);
        const float d01 = w1 - w0, d23 = w3 - w2;
        const float p01 = w0 + w1, p23 = w2 + w3;
        float4 q;
        q.x = act ? 0.25f * (d23 - d01) : 0.f;
        q.y = act ? 0.25f * (p23 - p01) : 0.f;
        q.z = act ? 0.25f * (d01 + d23) : 0.f;
        q.w = act ? 0.25f * (p01 + p23) : xv;
        s_uvrs[(S0 + i) * ROWS + lane] = q;
    }
}

__global__ void one_layer_net_kernel(const float* __restrict__ x,
                                     const float* __restrict__ weights,
                                     const float4* __restrict__ noise4,
                                     float* __restrict__ out) {
    extern __shared__ float4 s_uvrs[];   // [132][32] quadruples

    const int tid  = threadIdx.x;
    const int wrp  = tid >> 5;
    const int lane = tid & 31;

    if (wrp > 0) {
        // ------------------- PRODUCER WARPS (1..7), graded blocks ----------
        // w1: rows 0..5 (bar1) then 106..129 + pads (bar8)
        // w2: 6..13 (bar2)    w3: 14..25 (bar3)   w4: 26..41 (bar4)
        // w5: 42..61 (bar5)   w6: 62..81 (bar6)   w7: 82..105 (bar7)
        const bool act = (lane < NLUT);
        const int  nl  = act ? lane : 0;

        float4 wb = make_float4(0.f, 0.f, 0.f, 0.f);
        if (act) wb = reinterpret_cast<const float4*>(weights)[lane];
        const float c0 = fabsf(1.0f - fabsf(wb.x)) * 0.125f;
        const float c1 = fabsf(1.0f - fabsf(wb.y)) * 0.125f;
        const float c2 = fabsf(1.0f - fabsf(wb.z)) * 0.125f;
        const float c3 = fabsf(1.0f - fabsf(wb.w)) * 0.125f;
        const float xv = (lane == 27) ? x[0] : ((lane == 28) ? x[1] : 0.0f);

        int b;
        switch (wrp) {
        case 1:
            produce<0, 6>(noise4, s_uvrs, nl, act, wb, c0, c1, c2, c3, xv, lane);
            b = 1; BAR_ARRIVE(b);
            produce<106, 16>(noise4, s_uvrs, nl, act, wb, c0, c1, c2, c3, xv, lane);
            produce<122, 8>(noise4, s_uvrs, nl, act, wb, c0, c1, c2, c3, xv, lane);
            s_uvrs[130 * ROWS + lane] = make_float4(0.f, 0.f, 0.f, 0.f);
            s_uvrs[131 * ROWS + lane] = make_float4(0.f, 0.f, 0.f, 0.f);
            b = 8; BAR_ARRIVE(b);
            break;
        case 2:
            produce<6, 8>(noise4, s_uvrs, nl, act, wb, c0, c1, c2, c3, xv, lane);
            b = 2; BAR_ARRIVE(b);
            break;
        case 3:
            produce<14, 12>(noise4, s_uvrs, nl, act, wb, c0, c1, c2, c3, xv, lane);
            b = 3; BAR_ARRIVE(b);
            break;
        case 4:
            produce<26, 16>(noise4, s_uvrs, nl, act, wb, c0, c1, c2, c3, xv, lane);
            b = 4; BAR_ARRIVE(b);
            break;
        case 5:
            produce<42, 16>(noise4, s_uvrs, nl, act, wb, c0, c1, c2, c3, xv, lane);
            produce<58, 4>(noise4, s_uvrs, nl, act, wb, c0, c1, c2, c3, xv, lane);
            b = 5; BAR_ARRIVE(b);
            break;
        case 6:
            produce<62, 16>(noise4, s_uvrs, nl, act, wb, c0, c1, c2, c3, xv, lane);
            produce<78, 4>(noise4, s_uvrs, nl, act, wb, c0, c1, c2, c3, xv, lane);
            b = 6; BAR_ARRIVE(b);
            break;
        default:   // wrp == 7
            produce<82, 16>(noise4, s_uvrs, nl, act, wb, c0, c1, c2, c3, xv, lane);
            produce<98, 8>(noise4, s_uvrs, nl, act, wb, c0, c1, c2, c3, xv, lane);
            b = 7; BAR_ARRIVE(b);
            break;
        }
        return;
    }

    // ----------------------- CONSUMER WARP (0) — 1-step scan ---------------
    // Minimum MIO ops per step: 2 SHFL + 1 LDS.128 prefetch (2 rows ahead).
    const int sa = c_srcA[lane];
    const int sb = c_srcB[lane];

    float state = (lane < NLUT) ? -1.0f
                : (lane == 27) ? x[0]
                : (lane == 28) ? x[1] : 0.0f;

    // Hoist step-0's shfls above the first barrier (depend only on init state).
    float A = __shfl_sync(0xFFFFFFFFu, state, sa);
    float B = __shfl_sync(0xFFFFFFFFu, state, sb);

    int b = 1;
    BAR_WAIT(b);   // rows 0..5 ready

    const float4* pF = s_uvrs + lane;
    float4 q  = pF[0 * ROWS];   // row 0 (this step)
    float4 qn = pF[1 * ROWS];   // row 1 (next step)
    pF += 2 * ROWS;

    // Finish step 0.
    {
        const float4 qq = pF[0];  pF += ROWS;       // prefetch row 2
        state = fmaf(B, fmaf(A, q.x, q.y), fmaf(A, q.z, q.w));
        q = qn; qn = qq;
    }

#define STEP1()                                                              \
    do {                                                                     \
        A = __shfl_sync(0xFFFFFFFFu, state, sa);                             \
        B = __shfl_sync(0xFFFFFFFFu, state, sb);                             \
        const float4 qq = pF[0];  pF += ROWS;                                \
        state = fmaf(B, fmaf(A, q.x, q.y), fmaf(A, q.z, q.w));               \
        q = qn; qn = qq;                                                     \
    } while (0)

    // Step s consumes row s, prefetches row s+2 (needs rows <= s+2):
    //   steps 0..3    <=5   (bar1, step 0 done)   steps 4..11   <=13  (bar2)
    //   steps 12..23  <=25  (bar3)                steps 24..39  <=41  (bar4)
    //   steps 40..59  <=61  (bar5)                steps 60..79  <=81  (bar6)
    //   steps 80..103 <=105 (bar7)                steps 104..129 <=131 (bar8)
    STEP1(); STEP1(); STEP1();
    b = 2; BAR_WAIT(b);
#pragma unroll
    for (int i = 0; i < 8; ++i) STEP1();
    b = 3; BAR_WAIT(b);
#pragma unroll
    for (int i = 0; i < 12; ++i) STEP1();
    b = 4; BAR_WAIT(b);
#pragma unroll
    for (int i = 0; i < 16; ++i) STEP1();
    b = 5; BAR_WAIT(b);
#pragma unroll
    for (int i = 0; i < 20; ++i) STEP1();
    b = 6; BAR_WAIT(b);
#pragma unroll
    for (int i = 0; i < 20; ++i) STEP1();
    b = 7; BAR_WAIT(b);
#pragma unroll
    for (int i = 0; i < 24; ++i) STEP1();
    b = 8; BAR_WAIT(b);
#pragma unroll
    for (int i = 0; i < 26; ++i) STEP1();

    // Outputs: final[0,1] -> flat 1, final[1,2] -> flat 5, final[7,2] -> flat 23.
    if (lane == 1)  out[0] = state;
    if (lane == 5)  out[1] = state;
    if (lane == 23) out[2] = state;
}

extern "C" void kernel_launch(void* const* d_in, const int* in_sizes, int n_in,
                              void* d_out, int out_size) {
    (void)in_sizes; (void)n_in; (void)out_size;
    const float*  x  = (const float*)d_in[0];      // [2]
    const float*  w  = (const float*)d_in[1];      // [9,3,4]
    const float4* nz = (const float4*)d_in[2];     // [130,9,3,4] as float4
    float* out = (float*)d_out;                    // [3]

    const size_t smem = (size_t)UROWS * ROWS * sizeof(float4);   // 67584 B
    cudaFuncSetAttribute(one_layer_net_kernel,
                         cudaFuncAttributeMaxDynamicSharedMemorySize, (int)smem);
    one_layer_net_kernel<<<1, 256, smem>>>(x, w, nz, out);
}